// round 8
// baseline (speedup 1.0000x reference)
#include <cuda_runtime.h>
#include <cuda_bf16.h>
#include <cstdint>

// ---------------- problem constants ----------------
#define B_      2
#define NPIX    576
#define NL      171
#define NBL     342
#define NPAD    384          // padded N for GEMM2 (6 x 64)
#define ICH     768
#define OC1     512
#define OC2     512
#define M1      4608         // OC1*9
#define N1      1152         // B_*NPIX
#define K1      768
#define K2      4608
#define KSPLIT  12
#define IMG_ELEMS  (577*B_*768)
#define TXT_ELEMS  (B_*77*NL*512)

// ---------------- scratch (device globals; zero-initialized at load) ----------------
__device__ __align__(128) __nv_bfloat16 g_A1b[M1 * K1];   // w1 rearranged [m=oc1*9+ab][ic]
__device__ __align__(128) __nv_bfloat16 g_Bxb[N1 * K1];   // x transposed  [n][ic]
__device__ __align__(128) __nv_bfloat16 g_P1b[(size_t)N1 * M1];  // GEMM1 out, bf16
__device__ __align__(128) __nv_bfloat16 g_W2b[OC2 * K2];  // w2 cast (already K-major)
__device__ __align__(128) __nv_bfloat16 g_Tbb[NPAD * K2]; // [bl][k]; rows >=342 stay zero
__device__ __align__(128) float         g_part[KSPLIT * NPAD * OC2];
__device__ __align__(128) float         g_out512[NPAD * OC2];
__device__ int g_m[N1];

// ---------------- PTX helpers (sm_80 base-target features only) ----------------
__device__ __forceinline__ uint32_t smem_u32(const void* p) {
    uint32_t a;
    asm("{ .reg .u64 t; cvta.to.shared.u64 t, %1; cvt.u32.u64 %0, t; }" : "=r"(a) : "l"(p));
    return a;
}
__device__ __forceinline__ void cpasync16(uint32_t dst, const void* src) {
    asm volatile("cp.async.cg.shared.global [%0], [%1], 16;\n" :: "r"(dst), "l"(src));
}
#define CP_COMMIT() asm volatile("cp.async.commit_group;\n" ::: "memory")
#define CP_WAIT2()  asm volatile("cp.async.wait_group 2;\n" ::: "memory")
#define CP_WAIT0()  asm volatile("cp.async.wait_group 0;\n" ::: "memory")

__device__ __forceinline__ void ldsm_x4(uint32_t& r0, uint32_t& r1, uint32_t& r2,
                                        uint32_t& r3, uint32_t addr) {
    asm volatile("ldmatrix.sync.aligned.m8n8.x4.shared.b16 {%0,%1,%2,%3}, [%4];"
                 : "=r"(r0), "=r"(r1), "=r"(r2), "=r"(r3) : "r"(addr));
}
__device__ __forceinline__ void mma_bf16(float* c, const uint32_t* a, const uint32_t* b) {
    asm volatile("mma.sync.aligned.m16n8k16.row.col.f32.bf16.bf16.f32 "
                 "{%0,%1,%2,%3}, {%4,%5,%6,%7}, {%8,%9}, {%0,%1,%2,%3};"
                 : "+f"(c[0]), "+f"(c[1]), "+f"(c[2]), "+f"(c[3])
                 : "r"(a[0]), "r"(a[1]), "r"(a[2]), "r"(a[3]), "r"(b[0]), "r"(b[1]));
}

// output-type helpers
__device__ __forceinline__ void store_c(float* p, float v) { *p = v; }
__device__ __forceinline__ void store_c(__nv_bfloat16* p, float v) { *p = __float2bfloat16(v); }

// ---------------- labels ----------------
__global__ void labels_k(const int* __restrict__ targets) {
    int i = blockIdx.x * blockDim.x + threadIdx.x;
    if (i >= N1) return;
    int b = i / NPIX, pix = i % NPIX;
    int pi = pix / 24, qj = pix % 24;
    g_m[i] = targets[b * 147456 + (pi * 16) * 384 + qj * 16];
}

// ---------------- fused prep A: xpack (864 blocks) + w1r (512 blocks) ----------------
#define XPACK_BLOCKS (18 * 24 * 2)   // 864
__global__ __launch_bounds__(256) void prepA_k(const float* __restrict__ noise,
                                               const float* __restrict__ w1) {
    int bid = blockIdx.x;
    if (bid < XPACK_BLOCKS) {
        __shared__ float tile[32][33];
        int b = bid / (18 * 24);
        int r0 = bid % (18 * 24);
        int p0 = (r0 % 18) * 32, c0 = (r0 / 18) * 32;
        int tx = threadIdx.x & 31, ty = threadIdx.x >> 5;
        for (int r = ty; r < 32; r += 8)
            tile[r][tx] = noise[(size_t)b * 443136 + (c0 + r) * 577 + 1 + p0 + tx];
        __syncthreads();
        for (int r = ty; r < 32; r += 8)
            g_Bxb[(size_t)(b * NPIX + p0 + r) * ICH + c0 + tx] = __float2bfloat16(tile[tx][r]);
    } else {
        __shared__ float sm[ICH * 9];
        int oc1 = bid - XPACK_BLOCKS;
        const float4* src = (const float4*)(w1 + (size_t)oc1 * ICH * 9);
        for (int i = threadIdx.x; i < ICH * 9 / 4; i += 256)
            ((float4*)sm)[i] = src[i];
        __syncthreads();
        uint32_t* dst = (uint32_t*)(g_A1b + (size_t)oc1 * 9 * K1);
        for (int j2 = threadIdx.x; j2 < ICH * 9 / 2; j2 += 256) {
            int j = j2 * 2;
            int ab = j / ICH, ic = j - ab * ICH;
            __nv_bfloat162 v;
            v.x = __float2bfloat16(sm[ic * 9 + ab]);
            v.y = __float2bfloat16(sm[(ic + 1) * 9 + ab]);
            dst[j2] = *(uint32_t*)&v;
        }
    }
}

// ---------------- fused prep B: w2 cast (2304 blocks) + img transpose (912 blocks) ----------------
#define W2B_BLOCKS 2304
__global__ __launch_bounds__(256) void prepB_k(const float4* __restrict__ w2,
                                               const float* __restrict__ noise,
                                               float* __restrict__ out_img) {
    int bid = blockIdx.x;
    if (bid < W2B_BLOCKS) {
        int i = bid * 256 + threadIdx.x;
        float4 v = w2[i];
        __nv_bfloat162 lo, hi;
        lo.x = __float2bfloat16(v.x); lo.y = __float2bfloat16(v.y);
        hi.x = __float2bfloat16(v.z); hi.y = __float2bfloat16(v.w);
        uint2 o;
        o.x = *(uint32_t*)&lo; o.y = *(uint32_t*)&hi;
        ((uint2*)g_W2b)[i] = o;
    } else {
        __shared__ float tile[32][33];
        int t = bid - W2B_BLOCKS;            // 0..911 = 19*24*2
        int b = t / (19 * 24);
        int r0 = t % (19 * 24);
        int s0 = (r0 % 19) * 32, c0 = (r0 / 19) * 32;
        int tx = threadIdx.x & 31, ty = threadIdx.x >> 5;
        for (int r = ty; r < 32; r += 8) {
            int s = s0 + tx;
            if (s < 577) tile[r][tx] = noise[(size_t)b * 443136 + (c0 + r) * 577 + s];
        }
        __syncthreads();
        for (int r = ty; r < 32; r += 8) {
            int s = s0 + r;
            if (s < 577) out_img[(size_t)s * (B_ * 768) + b * 768 + c0 + tx] = tile[tx][r];
        }
    }
}

// ---------------- bf16 mma.sync GEMM:  C[n][m] = sum_k A[m][k]*B[n][k] ----------------
// 128(M)x64(N) block tile, BK=32, 256 threads (8 warps: 4 m x 2 n), warp tile 32x32.
// 4-stage cp.async ring, ONE __syncthreads per tile, loads issued 3 tiles ahead
// at the top of the tile body (maximize load->use distance).
#define BK      32
#define RSTRIDE 80    // 32 bf16 = 64B + 16B pad -> conflict-free ldmatrix (pitch/16 odd)
#define A_ROWS  128
#define B_ROWS  64
#define STAGES  4
#define STAGE_SZ ((A_ROWS + B_ROWS) * RSTRIDE)   // 15360
#define SMEM_SZ  (STAGES * STAGE_SZ)             // 61440

template <typename OutT>
__global__ __launch_bounds__(256) void gemm_bf16(
    const __nv_bfloat16* __restrict__ A, const __nv_bfloat16* __restrict__ B,
    OutT* __restrict__ C, int ldk, int ktiles, int ldC, int zstride)
{
    extern __shared__ __align__(128) char smem_raw[];
    const uint32_t sbase = smem_u32(smem_raw);
    const int tid = threadIdx.x;
    const int lane = tid & 31, wid = tid >> 5;
    const int wm = wid & 3, wn = wid >> 2;
    const int m0 = blockIdx.x * 128, n0 = blockIdx.y * 64;
    const int kofs = blockIdx.z * ktiles * BK;
    C += (size_t)blockIdx.z * zstride;

    float acc[2][4][4];
#pragma unroll
    for (int i = 0; i < 2; i++)
#pragma unroll
        for (int j = 0; j < 4; j++)
#pragma unroll
            for (int q = 0; q < 4; q++) acc[i][j][q] = 0.f;

    // one tile stage = (128 A rows + 64 B rows) x 32 bf16; 768 x 16B chunks
    auto load_tile = [&](int stage, int t) {
        uint32_t s = sbase + stage * STAGE_SZ;
        int k = kofs + t * BK;
#pragma unroll
        for (int i = 0; i < 3; i++) {
            int ch = tid + i * 256;        // 0..767 (A: 0..511, B: 512..767)
            int isB = ch >> 9;
            int row = (ch & 511) >> 2;
            int c4 = ch & 3;
            uint32_t dst = s + isB * (A_ROWS * RSTRIDE) + row * RSTRIDE + c4 * 16;
            const __nv_bfloat16* src =
                (isB ? B + (size_t)(n0 + row) * ldk : A + (size_t)(m0 + row) * ldk)
                + k + c4 * 8;
            cpasync16(dst, src);
        }
    };

    // prologue: fill 3 stages
    load_tile(0, 0); CP_COMMIT();
    if (ktiles > 1) load_tile(1, 1);
    CP_COMMIT();
    if (ktiles > 2) load_tile(2, 2);
    CP_COMMIT();

    const uint32_t rsel = lane & 15;
    const uint32_t chi = (lane >> 4) * 16;

    uint32_t aF[2][2][4];   // [ks][mt][4]
    uint32_t bF[2][4][2];   // [ks][nt][2]

    auto ld_frags = [&](int ks, uint32_t sA, uint32_t sB) {
        uint32_t colB = ks * 32 + chi;
#pragma unroll
        for (int mt = 0; mt < 2; mt++) {
            uint32_t addr = sA + (wm * 32 + mt * 16 + rsel) * RSTRIDE + colB;
            ldsm_x4(aF[ks][mt][0], aF[ks][mt][1], aF[ks][mt][2], aF[ks][mt][3], addr);
        }
#pragma unroll
        for (int p = 0; p < 2; p++) {
            uint32_t r0, r1, r2, r3;
            uint32_t addr = sB + (wn * 32 + p * 16 + rsel) * RSTRIDE + colB;
            ldsm_x4(r0, r1, r2, r3, addr);
            bF[ks][2 * p][0] = r0; bF[ks][2 * p][1] = r2;
            bF[ks][2 * p + 1][0] = r1; bF[ks][2 * p + 1][1] = r3;
        }
    };
    auto do_mma = [&](int ks) {
#pragma unroll
        for (int mt = 0; mt < 2; mt++)
#pragma unroll
            for (int nt = 0; nt < 4; nt++)
                mma_bf16(acc[mt][nt], aF[ks][mt], bF[ks][nt]);
    };

    for (int t = 0; t < ktiles; t++) {
        CP_WAIT2();              // stage t%STAGES complete (<=2 newer groups pending)
        __syncthreads();         // all warps done reading stage (t+3)%STAGES (iter t-1)

        // issue next load immediately -> ~3 tile periods to land
        if (t + STAGES - 1 < ktiles) load_tile((t + STAGES - 1) % STAGES, t + STAGES - 1);
        CP_COMMIT();             // unconditional: keeps group accounting uniform

        uint32_t sA = sbase + (t % STAGES) * STAGE_SZ;
        uint32_t sB = sA + A_ROWS * RSTRIDE;

        ld_frags(0, sA, sB);
        ld_frags(1, sA, sB);     // overlaps mma of ks=0 at issue level
        do_mma(0);
        do_mma(1);
    }

    const int mrow = lane >> 2, ncol = (lane & 3) * 2;
#pragma unroll
    for (int mt = 0; mt < 2; mt++)
#pragma unroll
        for (int nt = 0; nt < 4; nt++) {
            int m = m0 + wm * 32 + mt * 16 + mrow;
            int n = n0 + wn * 32 + nt * 8 + ncol;
            store_c(&C[(size_t)n * ldC + m],           acc[mt][nt][0]);
            store_c(&C[(size_t)(n + 1) * ldC + m],     acc[mt][nt][1]);
            store_c(&C[(size_t)n * ldC + m + 8],       acc[mt][nt][2]);
            store_c(&C[(size_t)(n + 1) * ldC + m + 8], acc[mt][nt][3]);
        }
}

// ---------------- sparse per-label box-sum accumulation -> g_Tbb[bl][k] ----------------
__global__ __launch_bounds__(512) void acc_kernel(const float* __restrict__ b1) {
    const int bl = blockIdx.x;
    const int b = bl / NL;
    const int l = bl % NL;
    const int oc1 = threadIdx.x;

    __shared__ int msh[NPIX];
    for (int i = threadIdx.x; i < NPIX; i += 512) msh[i] = g_m[b * NPIX + i];
    __syncthreads();

    const int lo[3][3] = {{0, 0, 1}, {0, 0, 1}, {3, 4, 5}};
    const int hi[3][3] = {{18, 19, 20}, {22, 23, 23}, {22, 23, 23}};

    float T9[9];
#pragma unroll
    for (int k = 0; k < 9; k++) T9[k] = 0.f;

    for (int pix = 0; pix < NPIX; pix++) {
        if (msh[pix] != l) continue;
        const __nv_bfloat16* v = &g_P1b[(size_t)(b * NPIX + pix) * M1 + oc1 * 9];
        float vv[9];
#pragma unroll
        for (int t = 0; t < 9; t++) vv[t] = __bfloat162float(v[t]);
        int p = pix / 24, q = pix % 24;

        float rs[3][3];
#pragma unroll
        for (int dr = 0; dr < 3; dr++)
#pragma unroll
            for (int bb = 0; bb < 3; bb++) {
                float s = 0.f;
#pragma unroll
                for (int a = 0; a < 3; a++)
                    if (p >= lo[dr][a] && p <= hi[dr][a]) s += vv[a * 3 + bb];
                rs[dr][bb] = s;
            }
#pragma unroll
        for (int dr = 0; dr < 3; dr++)
#pragma unroll
            for (int dc = 0; dc < 3; dc++) {
                float s = 0.f;
#pragma unroll
                for (int bb = 0; bb < 3; bb++)
                    if (q >= lo[dc][bb] && q <= hi[dc][bb]) s += rs[dr][bb];
                T9[dr * 3 + dc] += s;
            }
    }

    const float nrc[3] = {20.f, 24.f, 20.f};
    float bb1 = b1[oc1];
#pragma unroll
    for (int k = 0; k < 9; k++) {
        float t = (T9[k] + nrc[k / 3] * nrc[k % 3] * bb1) * (1.0f / 576.0f);
        g_Tbb[(size_t)bl * K2 + oc1 * 9 + k] = __float2bfloat16(t);
    }
}

// ---------------- split-K reduce + bias ----------------
__global__ void reduce_k(const float* __restrict__ b2) {
    int i = blockIdx.x * blockDim.x + threadIdx.x;
    if (i >= NPAD * OC2) return;
    const int S = NPAD * OC2;
    float s = 0.f;
#pragma unroll
    for (int z = 0; z < KSPLIT; z++) s += g_part[i + z * S];
    g_out512[i] = s + b2[i & 511];
}

// ---------------- final expansion (float4, streaming stores) ----------------
__global__ void expand_k(const float* __restrict__ w3, const float* __restrict__ b3,
                         float4* __restrict__ out) {
    int i4 = blockIdx.x * blockDim.x + threadIdx.x;
    if (i4 >= TXT_ELEMS / 4) return;
    int c4 = i4 & 127;
    int r = i4 >> 7;
    int l = r % NL;
    int r2 = r / NL;
    int o = r2 % 77;
    int b = r2 / 77;
    float w = __ldg(&w3[o]), bb = __ldg(&b3[o]);
    const float4 v = *(const float4*)&g_out512[((size_t)(b * NL + l) * OC2) + c4 * 4];
    __stcs(&out[i4], make_float4(w * v.x + bb, w * v.y + bb, w * v.z + bb, w * v.w + bb));
}

// ---------------- launch ----------------
extern "C" void kernel_launch(void* const* d_in, const int* in_sizes, int n_in,
                              void* d_out, int out_size) {
    const float* noise   = (const float*)d_in[0];
    const int*   targets = (const int*)  d_in[1];
    const float* w1      = (const float*)d_in[2];
    const float* b1      = (const float*)d_in[3];
    const float* w2      = (const float*)d_in[4];
    const float* b2      = (const float*)d_in[5];
    const float* w3      = (const float*)d_in[6];
    const float* b3      = (const float*)d_in[7];
    float* out      = (float*)d_out;
    float* out_img  = out;
    float* out_text = out + IMG_ELEMS;

    __nv_bfloat16 *pA1, *pBx, *pW2, *pTb, *pP1;
    float *pPart;
    cudaGetSymbolAddress((void**)&pA1,   g_A1b);
    cudaGetSymbolAddress((void**)&pBx,   g_Bxb);
    cudaGetSymbolAddress((void**)&pW2,   g_W2b);
    cudaGetSymbolAddress((void**)&pTb,   g_Tbb);
    cudaGetSymbolAddress((void**)&pP1,   g_P1b);
    cudaGetSymbolAddress((void**)&pPart, g_part);

    cudaFuncSetAttribute(gemm_bf16<__nv_bfloat16>,
                         cudaFuncAttributeMaxDynamicSharedMemorySize, SMEM_SZ);
    cudaFuncSetAttribute(gemm_bf16<float>,
                         cudaFuncAttributeMaxDynamicSharedMemorySize, SMEM_SZ);

    // launch order chosen so the 4th launch (ncu -s 5 target) is GEMM1.
    prepA_k<<<XPACK_BLOCKS + 512, 256>>>(noise, w1);                  // 1
    prepB_k<<<W2B_BLOCKS + 912, 256>>>((const float4*)w2, noise, out_img); // 2
    labels_k<<<2, 576>>>(targets);                                    // 3

    // 4: GEMM1: P1[n][m] = sum_ic A1b[m][ic] * Bxb[n][ic]   (1152 x 4608 x 768)
    gemm_bf16<__nv_bfloat16><<<dim3(M1 / 128, N1 / 64, 1), 256, SMEM_SZ>>>(
        pA1, pBx, pP1, K1, K1 / BK, M1, 0);

    // 5: sparse accumulation -> Tbb[bl][k]
    acc_kernel<<<NBL, 512>>>(b1);

    // 6: GEMM2 split-K: part[z][bl][oc2] = sum_{k chunk z} w2b[oc2][k] * Tbb[bl][k]
    gemm_bf16<float><<<dim3(OC2 / 128, NPAD / 64, KSPLIT), 256, SMEM_SZ>>>(
        pW2, pTb, pPart, K2, K2 / KSPLIT / BK, OC2, NPAD * OC2);
    reduce_k<<<(NPAD * OC2 + 255) / 256, 256>>>(b2);                  // 7

    expand_k<<<(TXT_ELEMS / 4 + 255) / 256, 256>>>(w3, b3, (float4*)out_text); // 8
}

// round 9
// speedup vs baseline: 1.1130x; 1.1130x over previous
#include <cuda_runtime.h>
#include <cuda_bf16.h>
#include <cstdint>

// ---------------- problem constants ----------------
#define B_      2
#define NPIX    576
#define NL      171
#define NBL     342
#define NPAD    384
#define ICH     768
#define OC1     512
#define OC2     512
#define K1      768
#define K2      4608
#define KSPLIT  12
#define IMG_ELEMS  (577*B_*768)
#define TXT_ELEMS  (B_*77*NL*512)

// pixel classes: interior rows/cols = [5,18] (14), edge = 10
// II: 196/batch, EI(p edge,q int): 140, IE: 140, EE: 100
// B-matrix row blocks (64-padded): II@0 (392->448), EI@448 (280->320), IE@768 (320), EE@1088 (200->256)
#define BX_ROWS 1344
// A-matrix row blocks: Wsum@0 (512), Wa@512 (1536), Wb@2048 (1536), Wfull@3584 (4608) -> 8192
#define AROWS   8192
// P output offsets (elems): II 448x512, EI 320x1536, IE 320x1536, EE 256x4608
#define P_II_OFF 0
#define P_EI_OFF 229376
#define P_IE_OFF 720896
#define P_EE_OFF 1212416
#define P_TOTAL  2392064

// ---------------- scratch ----------------
__device__ __align__(128) __nv_bfloat16 g_Aall[(size_t)AROWS * K1];
__device__ __align__(128) __nv_bfloat16 g_Bx2[(size_t)BX_ROWS * K1];  // pad rows stay 0
__device__ __align__(128) __nv_bfloat16 g_Pcat[P_TOTAL];
__device__ __align__(128) __nv_bfloat16 g_W2b[OC2 * K2];
__device__ __align__(128) __nv_bfloat16 g_Tbb[NPAD * K2];
__device__ __align__(128) float         g_part[KSPLIT * NPAD * OC2];
__device__ int g_m[B_ * NPIX];

// ---------------- PTX helpers ----------------
__device__ __forceinline__ uint32_t smem_u32(const void* p) {
    uint32_t a;
    asm("{ .reg .u64 t; cvta.to.shared.u64 t, %1; cvt.u32.u64 %0, t; }" : "=r"(a) : "l"(p));
    return a;
}
__device__ __forceinline__ void cpasync16(uint32_t dst, const void* src) {
    asm volatile("cp.async.cg.shared.global [%0], [%1], 16;\n" :: "r"(dst), "l"(src));
}
#define CP_COMMIT() asm volatile("cp.async.commit_group;\n" ::: "memory")

__device__ __forceinline__ void ldsm_x4(uint32_t& r0, uint32_t& r1, uint32_t& r2,
                                        uint32_t& r3, uint32_t addr) {
    asm volatile("ldmatrix.sync.aligned.m8n8.x4.shared.b16 {%0,%1,%2,%3}, [%4];"
                 : "=r"(r0), "=r"(r1), "=r"(r2), "=r"(r3) : "r"(addr));
}
__device__ __forceinline__ void mma_bf16(float* c, const uint32_t* a, const uint32_t* b) {
    asm volatile("mma.sync.aligned.m16n8k16.row.col.f32.bf16.bf16.f32 "
                 "{%0,%1,%2,%3}, {%4,%5,%6,%7}, {%8,%9}, {%0,%1,%2,%3};"
                 : "+f"(c[0]), "+f"(c[1]), "+f"(c[2]), "+f"(c[3])
                 : "r"(a[0]), "r"(a[1]), "r"(a[2]), "r"(a[3]), "r"(b[0]), "r"(b[1]));
}
__device__ __forceinline__ void store_c(float* p, float v) { *p = v; }
__device__ __forceinline__ void store_c(__nv_bfloat16* p, float v) { *p = __float2bfloat16(v); }

// pixel -> B-matrix row (class-sorted layout)
__device__ __forceinline__ int browmap(int b, int pix) {
    int p = pix / 24, q = pix % 24;
    bool Ip = (p >= 5 && p <= 18), Iq = (q >= 5 && q <= 18);
    int rep = (p < 5) ? p : p - 14;
    int req = (q < 5) ? q : q - 14;
    if (Ip && Iq)  return        b * 196 + (p - 5) * 14 + (q - 5);
    if (!Ip && Iq) return 448 +  b * 140 + rep * 14 + (q - 5);
    if (Ip)        return 768 +  b * 140 + (p - 5) * 10 + req;
    return 1088 + b * 100 + rep * 10 + req;
}

// ---------------- labels ----------------
__global__ void labels_k(const int* __restrict__ targets) {
    int i = blockIdx.x * blockDim.x + threadIdx.x;
    if (i >= B_ * NPIX) return;
    int b = i / NPIX, pix = i % NPIX;
    int pi = pix / 24, qj = pix % 24;
    g_m[i] = targets[b * 147456 + (pi * 16) * 384 + qj * 16];
}

// ---------------- fused prep A: xpack (864 blocks) + weight build (512 blocks) ----------------
#define XPACK_BLOCKS (18 * 24 * 2)
__global__ __launch_bounds__(256) void prepA_k(const float* __restrict__ noise,
                                               const float* __restrict__ w1) {
    int bid = blockIdx.x;
    if (bid < XPACK_BLOCKS) {
        __shared__ float tile[32][33];
        int b = bid / (18 * 24);
        int r0 = bid % (18 * 24);
        int p0 = (r0 % 18) * 32, c0 = (r0 / 18) * 32;
        int tx = threadIdx.x & 31, ty = threadIdx.x >> 5;
        for (int r = ty; r < 32; r += 8)
            tile[r][tx] = noise[(size_t)b * 443136 + (c0 + r) * 577 + 1 + p0 + tx];
        __syncthreads();
        for (int r = ty; r < 32; r += 8) {
            int dstrow = browmap(b, p0 + r);
            g_Bx2[(size_t)dstrow * K1 + c0 + tx] = __float2bfloat16(tile[tx][r]);
        }
    } else {
        __shared__ float sm[ICH * 9];
        int oc1 = bid - XPACK_BLOCKS;
        const float4* src = (const float4*)(w1 + (size_t)oc1 * ICH * 9);
        for (int i = threadIdx.x; i < ICH * 9 / 4; i += 256)
            ((float4*)sm)[i] = src[i];
        __syncthreads();
        for (int ic = threadIdx.x; ic < ICH; ic += 256) {
            float v[9];
#pragma unroll
            for (int t = 0; t < 9; t++) v[t] = sm[ic * 9 + t];
            float s9 = 0.f, va[3] = {0, 0, 0}, vb[3] = {0, 0, 0};
#pragma unroll
            for (int a = 0; a < 3; a++)
#pragma unroll
                for (int bb = 0; bb < 3; bb++) {
                    float x = v[a * 3 + bb];
                    s9 += x; va[a] += x; vb[bb] += x;
                }
            g_Aall[(size_t)oc1 * K1 + ic] = __float2bfloat16(s9);
#pragma unroll
            for (int a = 0; a < 3; a++)
                g_Aall[(size_t)(512 + oc1 * 3 + a) * K1 + ic] = __float2bfloat16(va[a]);
#pragma unroll
            for (int bb = 0; bb < 3; bb++)
                g_Aall[(size_t)(2048 + oc1 * 3 + bb) * K1 + ic] = __float2bfloat16(vb[bb]);
#pragma unroll
            for (int t = 0; t < 9; t++)
                g_Aall[(size_t)(3584 + oc1 * 9 + t) * K1 + ic] = __float2bfloat16(v[t]);
        }
    }
}

// ---------------- fused prep B: w2 cast + img transpose ----------------
#define W2B_BLOCKS 2304
__global__ __launch_bounds__(256) void prepB_k(const float4* __restrict__ w2,
                                               const float* __restrict__ noise,
                                               float* __restrict__ out_img) {
    int bid = blockIdx.x;
    if (bid < W2B_BLOCKS) {
        int i = bid * 256 + threadIdx.x;
        float4 v = w2[i];
        __nv_bfloat162 lo, hi;
        lo.x = __float2bfloat16(v.x); lo.y = __float2bfloat16(v.y);
        hi.x = __float2bfloat16(v.z); hi.y = __float2bfloat16(v.w);
        uint2 o;
        o.x = *(uint32_t*)&lo; o.y = *(uint32_t*)&hi;
        ((uint2*)g_W2b)[i] = o;
    } else {
        __shared__ float tile[32][33];
        int t = bid - W2B_BLOCKS;
        int b = t / (19 * 24);
        int r0 = t % (19 * 24);
        int s0 = (r0 % 19) * 32, c0 = (r0 / 19) * 32;
        int tx = threadIdx.x & 31, ty = threadIdx.x >> 5;
        for (int r = ty; r < 32; r += 8) {
            int s = s0 + tx;
            if (s < 577) tile[r][tx] = noise[(size_t)b * 443136 + (c0 + r) * 577 + s];
        }
        __syncthreads();
        for (int r = ty; r < 32; r += 8) {
            int s = s0 + r;
            if (s < 577) out_img[(size_t)s * (B_ * 768) + b * 768 + c0 + tx] = tile[tx][r];
        }
    }
}

// ---------------- GEMM core (round-7 best config: BK=64, 2-stage, frag double-buffer) ----------------
#define RSTRIDE 144
#define A_ROWS  128
#define B_ROWS  64
#define BUFSZ   ((A_ROWS + B_ROWS) * RSTRIDE)   // 27648
#define SMEM_SZ (2 * BUFSZ)                     // 55296

template <typename OutT>
__device__ __forceinline__ void gemm_core(
    const __nv_bfloat16* __restrict__ A,   // pre-offset to m0 row
    const __nv_bfloat16* __restrict__ B,   // pre-offset to n0 row
    OutT* __restrict__ C,                  // pre-offset to (n0,m0)
    int ldk, int ktiles, int ldC, uint32_t sbase)
{
    const int tid = threadIdx.x;
    const int lane = tid & 31, wid = tid >> 5;
    const int wm = wid & 3, wn = wid >> 2;

    float acc[2][4][4];
#pragma unroll
    for (int i = 0; i < 2; i++)
#pragma unroll
        for (int j = 0; j < 4; j++)
#pragma unroll
            for (int q = 0; q < 4; q++) acc[i][j][q] = 0.f;

    auto load_tile = [&](int buf, int t) {
        uint32_t s = sbase + buf * BUFSZ;
        int k = t * 64;
#pragma unroll
        for (int i = 0; i < 6; i++) {
            int ch = tid + i * 256;
            int isB = ch >> 10;
            int row = (ch >> 3) & (isB ? 63 : 127);
            int c8 = ch & 7;
            uint32_t dst = s + isB * (A_ROWS * RSTRIDE) + row * RSTRIDE + c8 * 16;
            const __nv_bfloat16* src =
                (isB ? B + (size_t)row * ldk : A + (size_t)row * ldk) + k + c8 * 8;
            cpasync16(dst, src);
        }
    };

    load_tile(0, 0);
    CP_COMMIT();
    if (ktiles > 1) { load_tile(1, 1); }
    CP_COMMIT();

    const uint32_t rsel = lane & 15;
    const uint32_t chi = (lane >> 4) * 16;

    uint32_t aF[2][2][4];
    uint32_t bF[2][4][2];

    auto ld_frags = [&](int fb, uint32_t sA, uint32_t sB, int ks) {
        uint32_t colB = ks * 32 + chi;
#pragma unroll
        for (int mt = 0; mt < 2; mt++) {
            uint32_t addr = sA + (wm * 32 + mt * 16 + rsel) * RSTRIDE + colB;
            ldsm_x4(aF[fb][mt][0], aF[fb][mt][1], aF[fb][mt][2], aF[fb][mt][3], addr);
        }
#pragma unroll
        for (int p = 0; p < 2; p++) {
            uint32_t r0, r1, r2, r3;
            uint32_t addr = sB + (wn * 32 + p * 16 + rsel) * RSTRIDE + colB;
            ldsm_x4(r0, r1, r2, r3, addr);
            bF[fb][2 * p][0] = r0; bF[fb][2 * p][1] = r2;
            bF[fb][2 * p + 1][0] = r1; bF[fb][2 * p + 1][1] = r3;
        }
    };
    auto do_mma = [&](int fb) {
#pragma unroll
        for (int mt = 0; mt < 2; mt++)
#pragma unroll
            for (int nt = 0; nt < 4; nt++)
                mma_bf16(acc[mt][nt], aF[fb][mt], bF[fb][nt]);
    };

    for (int t = 0; t < ktiles; t++) {
        if (t + 1 < ktiles)
            asm volatile("cp.async.wait_group 1;\n" ::: "memory");
        else
            asm volatile("cp.async.wait_group 0;\n" ::: "memory");
        __syncthreads();

        int buf = t & 1;
        uint32_t sA = sbase + buf * BUFSZ;
        uint32_t sB = sA + A_ROWS * RSTRIDE;

        ld_frags(0, sA, sB, 0);
        ld_frags(1, sA, sB, 1);
        do_mma(0);
        ld_frags(0, sA, sB, 2);
        do_mma(1);
        ld_frags(1, sA, sB, 3);
        do_mma(0);
        __syncthreads();
        if (t + 2 < ktiles) {
            load_tile(buf, t + 2);
            CP_COMMIT();
        }
        do_mma(1);
    }

    const int mrow = lane >> 2, ncol = (lane & 3) * 2;
#pragma unroll
    for (int mt = 0; mt < 2; mt++)
#pragma unroll
        for (int nt = 0; nt < 4; nt++) {
            int m = wm * 32 + mt * 16 + mrow;
            int n = wn * 32 + nt * 8 + ncol;
            store_c(&C[(size_t)n * ldC + m],           acc[mt][nt][0]);
            store_c(&C[(size_t)(n + 1) * ldC + m],     acc[mt][nt][1]);
            store_c(&C[(size_t)n * ldC + m + 8],       acc[mt][nt][2]);
            store_c(&C[(size_t)(n + 1) * ldC + m + 8], acc[mt][nt][3]);
        }
}

// segmented GEMM1: 4 class-segments in one launch. 292 CTAs.
__global__ __launch_bounds__(256) void gemm_seg_k() {
    extern __shared__ __align__(128) char smem_raw[];
    uint32_t sbase = smem_u32(smem_raw);
    int bid = blockIdx.x;
    int seg = (bid < 28) ? 0 : (bid < 88) ? 1 : (bid < 148) ? 2 : 3;
    const int segStart[4] = {0, 28, 88, 148};
    const int segMt[4]    = {4, 12, 12, 36};
    const int segArow[4]  = {0, 512, 2048, 3584};
    const int segBrow[4]  = {0, 448, 768, 1088};
    const int segCoff[4]  = {P_II_OFF, P_EI_OFF, P_IE_OFF, P_EE_OFF};
    const int segLd[4]    = {512, 1536, 1536, 4608};
    int local = bid - segStart[seg];
    int bx = local % segMt[seg], by = local / segMt[seg];
    int m0 = bx * 128, n0 = by * 64;
    const __nv_bfloat16* A = g_Aall + (size_t)(segArow[seg] + m0) * K1;
    const __nv_bfloat16* B = g_Bx2 + (size_t)(segBrow[seg] + n0) * K1;
    __nv_bfloat16* C = g_Pcat + segCoff[seg] + (size_t)n0 * segLd[seg] + m0;
    gemm_core<__nv_bfloat16>(A, B, C, K1, K1 / 64, segLd[seg], sbase);
}

// GEMM2 split-K (unchanged math)
__global__ __launch_bounds__(256) void gemm2_k() {
    extern __shared__ __align__(128) char smem_raw[];
    uint32_t sbase = smem_u32(smem_raw);
    int m0 = blockIdx.x * 128, n0 = blockIdx.y * 64;
    int z = blockIdx.z;
    int kt = K2 / KSPLIT / 64;   // 6
    const __nv_bfloat16* A = g_W2b + (size_t)m0 * K2 + z * kt * 64;
    const __nv_bfloat16* B = g_Tbb + (size_t)n0 * K2 + z * kt * 64;
    float* C = g_part + (size_t)z * NPAD * OC2 + (size_t)n0 * OC2 + m0;
    gemm_core<float>(A, B, C, K2, kt, OC2, sbase);
}

// ---------------- sparse per-label accumulation (class-aware) -> g_Tbb[bl][k] ----------------
__global__ __launch_bounds__(512) void acc_kernel(const float* __restrict__ b1) {
    const int bl = blockIdx.x;
    const int b = bl / NL;
    const int l = bl % NL;
    const int oc1 = threadIdx.x;

    __shared__ int msh[NPIX];
    for (int i = threadIdx.x; i < NPIX; i += 512) msh[i] = g_m[b * NPIX + i];
    __syncthreads();

    const int lo[3][3] = {{0, 0, 1}, {0, 0, 1}, {3, 4, 5}};
    const int hi[3][3] = {{18, 19, 20}, {22, 23, 23}, {22, 23, 23}};

    float T9[9];
#pragma unroll
    for (int k = 0; k < 9; k++) T9[k] = 0.f;

    for (int pix = 0; pix < NPIX; pix++) {
        if (msh[pix] != l) continue;
        int p = pix / 24, q = pix % 24;
        bool Ip = (p >= 5 && p <= 18), Iq = (q >= 5 && q <= 18);
        int rep = (p < 5) ? p : p - 14;
        int req = (q < 5) ? q : q - 14;

        if (Ip && Iq) {
            int slot = b * 196 + (p - 5) * 14 + (q - 5);
            float s = __bfloat162float(g_Pcat[P_II_OFF + (size_t)slot * 512 + oc1]);
#pragma unroll
            for (int k = 0; k < 9; k++) T9[k] += s;
        } else if (!Ip && Iq) {
            int slot = b * 140 + rep * 14 + (q - 5);
            const __nv_bfloat16* v = &g_Pcat[P_EI_OFF + (size_t)slot * 1536 + oc1 * 3];
            float ra[3];
#pragma unroll
            for (int a = 0; a < 3; a++) ra[a] = __bfloat162float(v[a]);
#pragma unroll
            for (int dr = 0; dr < 3; dr++) {
                float s = 0.f;
#pragma unroll
                for (int a = 0; a < 3; a++)
                    if (p >= lo[dr][a] && p <= hi[dr][a]) s += ra[a];
                T9[dr * 3 + 0] += s; T9[dr * 3 + 1] += s; T9[dr * 3 + 2] += s;
            }
        } else if (Ip) {
            int slot = b * 140 + (p - 5) * 10 + req;
            const __nv_bfloat16* v = &g_Pcat[P_IE_OFF + (size_t)slot * 1536 + oc1 * 3];
            float rb[3];
#pragma unroll
            for (int bb = 0; bb < 3; bb++) rb[bb] = __bfloat162float(v[bb]);
#pragma unroll
            for (int dc = 0; dc < 3; dc++) {
                float s = 0.f;
#pragma unroll
                for (int bb = 0; bb < 3; bb++)
                    if (q >= lo[dc][bb] && q <= hi[dc][bb]) s += rb[bb];
                T9[0 + dc] += s; T9[3 + dc] += s; T9[6 + dc] += s;
            }
        } else {
            int slot = b * 100 + rep * 10 + req;
            const __nv_bfloat16* v = &g_Pcat[P_EE_OFF + (size_t)slot * 4608 + oc1 * 9];
            float vv[9];
#pragma unroll
            for (int t = 0; t < 9; t++) vv[t] = __bfloat162float(v[t]);
            float rs[3][3];
#pragma unroll
            for (int dr = 0; dr < 3; dr++)
#pragma unroll
                for (int bb = 0; bb < 3; bb++) {
                    float s = 0.f;
#pragma unroll
                    for (int a = 0; a < 3; a++)
                        if (p >= lo[dr][a] && p <= hi[dr][a]) s += vv[a * 3 + bb];
                    rs[dr][bb] = s;
                }
#pragma unroll
            for (int dr = 0; dr < 3; dr++)
#pragma unroll
                for (int dc = 0; dc < 3; dc++) {
                    float s = 0.f;
#pragma unroll
                    for (int bb = 0; bb < 3; bb++)
                        if (q >= lo[dc][bb] && q <= hi[dc][bb]) s += rs[dr][bb];
                    T9[dr * 3 + dc] += s;
                }
        }
    }

    const float nrc[3] = {20.f, 24.f, 20.f};
    float bb1 = b1[oc1];
#pragma unroll
    for (int k = 0; k < 9; k++) {
        float t = (T9[k] + nrc[k / 3] * nrc[k % 3] * bb1) * (1.0f / 576.0f);
        g_Tbb[(size_t)bl * K2 + oc1 * 9 + k] = __float2bfloat16(t);
    }
}

// ---------------- fused reduce + expand: block = (b,l), thread = channel ----------------
__global__ __launch_bounds__(512) void expand2_k(const float* __restrict__ w3,
                                                 const float* __restrict__ b3,
                                                 const float* __restrict__ b2,
                                                 float* __restrict__ out) {
    int bl = blockIdx.x;
    int b = bl / NL, l = bl % NL;
    int c = threadIdx.x;
    const int S = NPAD * OC2;
    float s = b2[c];
#pragma unroll
    for (int z = 0; z < KSPLIT; z++) s += g_part[(size_t)z * S + bl * OC2 + c];
    size_t base = ((size_t)b * 77 * NL + l) * 512 + c;
    for (int o = 0; o < 77; o++) {
        float v = w3[o] * s + b3[o];
        __stcs(&out[base + (size_t)o * NL * 512], v);
    }
}

// ---------------- launch ----------------
extern "C" void kernel_launch(void* const* d_in, const int* in_sizes, int n_in,
                              void* d_out, int out_size) {
    const float* noise   = (const float*)d_in[0];
    const int*   targets = (const int*)  d_in[1];
    const float* w1      = (const float*)d_in[2];
    const float* b1      = (const float*)d_in[3];
    const float* w2      = (const float*)d_in[4];
    const float* b2      = (const float*)d_in[5];
    const float* w3      = (const float*)d_in[6];
    const float* b3      = (const float*)d_in[7];
    float* out      = (float*)d_out;
    float* out_img  = out;
    float* out_text = out + IMG_ELEMS;

    cudaFuncSetAttribute(gemm_seg_k, cudaFuncAttributeMaxDynamicSharedMemorySize, SMEM_SZ);
    cudaFuncSetAttribute(gemm2_k,    cudaFuncAttributeMaxDynamicSharedMemorySize, SMEM_SZ);

    prepA_k<<<XPACK_BLOCKS + 512, 256>>>(noise, w1);                       // 1
    prepB_k<<<W2B_BLOCKS + 912, 256>>>((const float4*)w2, noise, out_img); // 2
    labels_k<<<(B_ * NPIX + 255) / 256, 256>>>(targets);                   // 3

    gemm_seg_k<<<292, 256, SMEM_SZ>>>();                                   // 4 (profiled)
    acc_kernel<<<NBL, 512>>>(b1);                                          // 5
    gemm2_k<<<dim3(OC2 / 128, NPAD / 64, KSPLIT), 256, SMEM_SZ>>>();       // 6
    expand2_k<<<NBL, 512>>>(w3, b3, b2, out_text);                         // 7
}